// round 1
// baseline (speedup 1.0000x reference)
#include <cuda_runtime.h>

// Problem constants (fixed by setup_inputs)
#define BB   4
#define NG   4096
#define DZ   128
#define NT   2048
#define NK   2
#define TT   32      // t-tile per block
#define GT   32      // g-chunk
#define NTHR 256

// Fast exp2 on the FMA/ALU pipes (avoids MUFU bottleneck).
// Input y <= 0, pre-clamped to >= -125. Rel err ~3e-7.
__device__ __forceinline__ float fast_exp2(float y) {
    float z = y + 12582912.0f;            // 1.5*2^23: RNE round-to-int in mantissa
    float n = z - 12582912.0f;            // n = rint(y)
    float f = y - n;                      // f in [-0.5, 0.5]
    // 2^f, degree-5 Taylor in ln2 (Horner)
    float p = 1.3333558146e-3f;
    p = fmaf(p, f, 9.6181291076e-3f);
    p = fmaf(p, f, 5.5504108664e-2f);
    p = fmaf(p, f, 2.4022650696e-1f);
    p = fmaf(p, f, 6.9314718056e-1f);
    p = fmaf(p, f, 1.0f);
    // scale by 2^n via exponent-bit splice:
    // bits(z) = 0x4B400000 + n  =>  ((bits(z) << 23) + 0x3F800000) == bits(2^n)
    float s = __int_as_float((__float_as_int(z) << 23) + 0x3F800000);
    return p * s;
}

__global__ void __launch_bounds__(NTHR)
setconv_kernel(const float* __restrict__ x_grid,   // (B, NG, 2)
               const float* __restrict__ z_grid,   // (B, NG, 128)
               const float* __restrict__ xt,       // (B, NT, 2)
               const float* __restrict__ lsp,      // (2, 2)  [d*NK + k]
               float* __restrict__ out)            // (B, NT, 256)  c = z*NK + k
{
    __shared__ float4 zs[GT][DZ / 4];   // 16 KB: zg chunk
    __shared__ float2 ws[TT][GT];       //  8 KB: weights (k0,k1)
    __shared__ float2 xts[TT];
    __shared__ float2 xgs[GT];

    const int b  = blockIdx.x / (NT / TT);
    const int t0 = (blockIdx.x % (NT / TT)) * TT;
    const int tid = threadIdx.x;
    const int tx = tid & 31;   // channel group: channels tx*8 .. tx*8+7  (z = tx*4..tx*4+3)
    const int ty = tid >> 5;   // t group: t = t0 + ty*4 + i

    // Lengthscale -> exp2 coefficients (uniform across threads; tiny cost)
    float cx0, cx1, cy0, cy1;
    {
        float l00 = 1e-5f + log1pf(expf(lsp[0]));   // d=0,k=0
        float l01 = 1e-5f + log1pf(expf(lsp[1]));   // d=0,k=1
        float l10 = 1e-5f + log1pf(expf(lsp[2]));   // d=1,k=0
        float l11 = 1e-5f + log1pf(expf(lsp[3]));   // d=1,k=1
        const float c = -0.5f * 1.44269504088896340736f;  // -0.5*log2(e)
        cx0 = c / (l00 * l00);  cx1 = c / (l01 * l01);
        cy0 = c / (l10 * l10);  cy1 = c / (l11 * l11);
    }

    // xt tile for this block
    if (tid < TT) {
        xts[tid] = ((const float2*)xt)[(size_t)b * NT + t0 + tid];
    }

    float acc[4][8];
    #pragma unroll
    for (int i = 0; i < 4; i++)
        #pragma unroll
        for (int j = 0; j < 8; j++) acc[i][j] = 0.0f;

    const float4* zg_b = (const float4*)(z_grid + (size_t)b * NG * DZ);
    const float2* xg_b = ((const float2*)x_grid) + (size_t)b * NG;

    for (int g0 = 0; g0 < NG; g0 += GT) {
        __syncthreads();   // protect zs/ws from previous iteration's readers

        // Load zg chunk: GT*DZ floats = 1024 float4, coalesced
        #pragma unroll
        for (int i = 0; i < 4; i++) {
            int idx = tid + i * NTHR;                 // 0..1023
            ((float4*)zs)[idx] = zg_b[(size_t)g0 * (DZ / 4) + idx];
        }
        if (tid < GT) xgs[tid] = xg_b[g0 + tid];
        __syncthreads();

        // Weight generation: thread covers t = tid>>3, g = (tid&7)*4 + j
        {
            int t  = tid >> 3;
            int gb = (tid & 7) * 4;
            float2 xtv = xts[t];
            #pragma unroll
            for (int j = 0; j < 4; j++) {
                float2 xgv = xgs[gb + j];
                float dx = xtv.x - xgv.x;
                float dy = xtv.y - xgv.y;
                float dx2 = dx * dx;
                float dy2 = dy * dy;
                float y0 = fmaxf(fmaf(dx2, cx0, dy2 * cy0), -125.0f);
                float y1 = fmaxf(fmaf(dx2, cx1, dy2 * cy1), -125.0f);
                ws[t][gb + j] = make_float2(fast_exp2(y0), fast_exp2(y1));
            }
        }
        __syncthreads();

        // Accumulate: per g, 1 LDS.128 (conflict-free) + 4 LDS.64 (broadcast) + 32 FFMA
        #pragma unroll 8
        for (int g = 0; g < GT; g++) {
            float4 zv = zs[g][tx];
            #pragma unroll
            for (int i = 0; i < 4; i++) {
                float2 w = ws[ty * 4 + i][g];
                acc[i][0] = fmaf(w.x, zv.x, acc[i][0]);
                acc[i][1] = fmaf(w.y, zv.x, acc[i][1]);
                acc[i][2] = fmaf(w.x, zv.y, acc[i][2]);
                acc[i][3] = fmaf(w.y, zv.y, acc[i][3]);
                acc[i][4] = fmaf(w.x, zv.z, acc[i][4]);
                acc[i][5] = fmaf(w.y, zv.z, acc[i][5]);
                acc[i][6] = fmaf(w.x, zv.w, acc[i][6]);
                acc[i][7] = fmaf(w.y, zv.w, acc[i][7]);
            }
        }
    }

    // Write out: t = t0 + ty*4 + i, channels tx*8 .. tx*8+7 (two float4 stores)
    float4* out4 = (float4*)(out + ((size_t)b * NT + t0) * (DZ * NK));
    #pragma unroll
    for (int i = 0; i < 4; i++) {
        int t = ty * 4 + i;
        out4[t * 64 + tx * 2 + 0] = make_float4(acc[i][0], acc[i][1], acc[i][2], acc[i][3]);
        out4[t * 64 + tx * 2 + 1] = make_float4(acc[i][4], acc[i][5], acc[i][6], acc[i][7]);
    }
}

extern "C" void kernel_launch(void* const* d_in, const int* in_sizes, int n_in,
                              void* d_out, int out_size) {
    (void)in_sizes; (void)n_in; (void)out_size;
    const float* x_grid = (const float*)d_in[0];
    const float* z_grid = (const float*)d_in[1];
    const float* xt     = (const float*)d_in[2];
    const float* lsp    = (const float*)d_in[3];
    float* out = (float*)d_out;

    dim3 grid(BB * (NT / TT));
    dim3 block(NTHR);
    setconv_kernel<<<grid, block>>>(x_grid, z_grid, xt, lsp, out);
}

// round 7
// speedup vs baseline: 1.0632x; 1.0632x over previous
#include <cuda_runtime.h>

// Problem constants (fixed by setup_inputs)
#define BB   4
#define NG   4096
#define DZ   128
#define NT   2048
#define NK   2
#define TT   32      // t-tile per block
#define GT   32      // g-chunk
#define NTHR 256

typedef unsigned long long ull;

// ---- packed f32x2 helpers (sm_100+ PTX) ----
__device__ __forceinline__ ull pk(float lo, float hi) {
    ull r; asm("mov.b64 %0,{%1,%2};" : "=l"(r) : "f"(lo), "f"(hi)); return r;
}
__device__ __forceinline__ void upk(ull v, float& lo, float& hi) {
    asm("mov.b64 {%0,%1},%2;" : "=f"(lo), "=f"(hi) : "l"(v));
}
__device__ __forceinline__ ull fma2(ull a, ull b, ull c) {
    ull r; asm("fma.rn.f32x2 %0,%1,%2,%3;" : "=l"(r) : "l"(a), "l"(b), "l"(c)); return r;
}
__device__ __forceinline__ ull add2(ull a, ull b) {
    ull r; asm("add.rn.f32x2 %0,%1,%2;" : "=l"(r) : "l"(a), "l"(b)); return r;
}
__device__ __forceinline__ ull mul2(ull a, ull b) {
    ull r; asm("mul.rn.f32x2 %0,%1,%2;" : "=l"(r) : "l"(a), "l"(b)); return r;
}

__global__ void __launch_bounds__(NTHR)
setconv_kernel(const float* __restrict__ x_grid,   // (B, NG, 2)
               const float* __restrict__ z_grid,   // (B, NG, 128)
               const float* __restrict__ xt,       // (B, NT, 2)
               const float* __restrict__ lsp,      // (2, 2)  [d*NK + k]
               float* __restrict__ out)            // (B, NT, 256)  c = z*NK + k
{
    __shared__ float4 zs[GT][DZ / 4];       // 16 KB: zg chunk
    __shared__ float2 ws[TT][GT + 2];       // 8.5 KB: weights (k0,k1), padded rows
    __shared__ float2 xts[TT];
    __shared__ float2 xgs[GT];

    const int b  = blockIdx.x / (NT / TT);
    const int t0 = (blockIdx.x % (NT / TT)) * TT;
    const int tid = threadIdx.x;
    const int tx = tid & 31;   // channel group: z = tx*4 .. tx*4+3 (x NK)
    const int ty = tid >> 5;   // t group: t = t0 + ty*4 + i

    // Lengthscale -> exp2 coefficient pairs (uniform; tiny cost)
    ull cxp, cyp;
    {
        float l00 = 1e-5f + log1pf(expf(lsp[0]));   // d=0,k=0
        float l01 = 1e-5f + log1pf(expf(lsp[1]));   // d=0,k=1
        float l10 = 1e-5f + log1pf(expf(lsp[2]));   // d=1,k=0
        float l11 = 1e-5f + log1pf(expf(lsp[3]));   // d=1,k=1
        const float c = -0.5f * 1.44269504088896340736f;  // -0.5*log2(e)
        cxp = pk(c / (l00 * l00), c / (l01 * l01));
        cyp = pk(c / (l10 * l10), c / (l11 * l11));
    }
    // packed exp2 constants
    const ull KK   = pk(12582912.0f, 12582912.0f);     // 1.5*2^23
    const ull NEG1 = pk(-1.0f, -1.0f);
    const ull C5 = pk(1.3333558146e-3f, 1.3333558146e-3f);
    const ull C4 = pk(9.6181291076e-3f, 9.6181291076e-3f);
    const ull C3 = pk(5.5504108664e-2f, 5.5504108664e-2f);
    const ull C2 = pk(2.4022650696e-1f, 2.4022650696e-1f);
    const ull C1 = pk(6.9314718056e-1f, 6.9314718056e-1f);
    const ull C0 = pk(1.0f, 1.0f);

    if (tid < TT) {
        xts[tid] = ((const float2*)xt)[(size_t)b * NT + t0 + tid];
    }

    ull acc[4][4];   // [t-sub][z-sub] packed (k0,k1); bits 0 == (0.0f,0.0f)
    #pragma unroll
    for (int i = 0; i < 4; i++)
        #pragma unroll
        for (int j = 0; j < 4; j++) acc[i][j] = 0ull;

    const float4* zg_b = (const float4*)(z_grid + (size_t)b * NG * DZ);
    const float2* xg_b = ((const float2*)x_grid) + (size_t)b * NG;

    const int wt = tid >> 3;          // weight-gen t
    const int wg0 = (tid & 7) * 4;    // weight-gen g base
    const int t4 = ty * 4;

    for (int g0 = 0; g0 < NG; g0 += GT) {
        __syncthreads();   // protect zs/ws from previous iteration's readers

        // Load zg chunk: GT*DZ floats = 1024 float4, coalesced
        #pragma unroll
        for (int i = 0; i < 4; i++) {
            int idx = tid + i * NTHR;                 // 0..1023
            ((float4*)zs)[idx] = zg_b[(size_t)g0 * (DZ / 4) + idx];
        }
        if (tid < GT) xgs[tid] = xg_b[g0 + tid];
        __syncthreads();

        // Weight generation: thread covers t = tid>>3, g = (tid&7)*4 + j
        {
            float2 xtv = xts[wt];
            #pragma unroll
            for (int j = 0; j < 4; j++) {
                float2 xgv = xgs[wg0 + j];
                float dx = xtv.x - xgv.x;
                float dy = xtv.y - xgv.y;
                ull dx2 = pk(dx * dx, dx * dx);
                ull dy2 = pk(dy * dy, dy * dy);
                ull y = fma2(dx2, cxp, mul2(dy2, cyp));
                // clamp halves to >= -125
                float ylo, yhi; upk(y, ylo, yhi);
                y = pk(fmaxf(ylo, -125.0f), fmaxf(yhi, -125.0f));
                // packed exp2: n = rint(y) via magic constant, f = y - n
                ull z2 = add2(y, KK);           // rn(y + K); mantissa holds n
                ull n2 = fma2(KK, NEG1, z2);    // n = z2 - K   (exact, Sterbenz)
                ull f  = fma2(n2, NEG1, y);     // f = y - n    in [-0.5, 0.5]
                ull p = C5;
                p = fma2(p, f, C4);
                p = fma2(p, f, C3);
                p = fma2(p, f, C2);
                p = fma2(p, f, C1);
                p = fma2(p, f, C0);
                // exponent splice per half: bits(z2)= 0x4B400000 + n
                float zl, zh; upk(z2, zl, zh);
                float sl = __int_as_float((__float_as_int(zl) << 23) + 0x3F800000);
                float sh = __int_as_float((__float_as_int(zh) << 23) + 0x3F800000);
                ull r = mul2(p, pk(sl, sh));
                *(ull*)&ws[wt][wg0 + j] = r;
            }
        }
        __syncthreads();

        // Accumulate: per 2 g: 2 LDS.128 (z) + 4 LDS.128 (w broadcast) + 32 FFMA2
        #pragma unroll 8
        for (int h = 0; h < GT / 2; h++) {
            float4 za = zs[2 * h + 0][tx];
            float4 zb = zs[2 * h + 1][tx];
            ull za0 = pk(za.x, za.x), za1 = pk(za.y, za.y);
            ull za2 = pk(za.z, za.z), za3 = pk(za.w, za.w);
            ull zb0 = pk(zb.x, zb.x), zb1 = pk(zb.y, zb.y);
            ull zb2 = pk(zb.z, zb.z), zb3 = pk(zb.w, zb.w);
            #pragma unroll
            for (int i = 0; i < 4; i++) {
                ulonglong2 w = *(const ulonglong2*)&ws[t4 + i][2 * h];
                acc[i][0] = fma2(w.x, za0, acc[i][0]);
                acc[i][1] = fma2(w.x, za1, acc[i][1]);
                acc[i][2] = fma2(w.x, za2, acc[i][2]);
                acc[i][3] = fma2(w.x, za3, acc[i][3]);
                acc[i][0] = fma2(w.y, zb0, acc[i][0]);
                acc[i][1] = fma2(w.y, zb1, acc[i][1]);
                acc[i][2] = fma2(w.y, zb2, acc[i][2]);
                acc[i][3] = fma2(w.y, zb3, acc[i][3]);
            }
        }
    }

    // Write out: t = t0 + t4 + i, float2-pairs (k0,k1) at channel-pair index tx*4+z
    ull* out8 = (ull*)out + ((size_t)b * NT + t0) * (DZ * NK / 2);
    #pragma unroll
    for (int i = 0; i < 4; i++) {
        int t = t4 + i;
        ulonglong2 v0; v0.x = acc[i][0]; v0.y = acc[i][1];
        ulonglong2 v1; v1.x = acc[i][2]; v1.y = acc[i][3];
        *(ulonglong2*)&out8[t * 128 + tx * 4 + 0] = v0;
        *(ulonglong2*)&out8[t * 128 + tx * 4 + 2] = v1;
    }
}

extern "C" void kernel_launch(void* const* d_in, const int* in_sizes, int n_in,
                              void* d_out, int out_size) {
    (void)in_sizes; (void)n_in; (void)out_size;
    const float* x_grid = (const float*)d_in[0];
    const float* z_grid = (const float*)d_in[1];
    const float* xt     = (const float*)d_in[2];
    const float* lsp    = (const float*)d_in[3];
    float* out = (float*)d_out;

    dim3 grid(BB * (NT / TT));
    dim3 block(NTHR);
    setconv_kernel<<<grid, block>>>(x_grid, z_grid, xt, lsp, out);
}

// round 13
// speedup vs baseline: 3.0787x; 2.8956x over previous
#include <cuda_runtime.h>
#include <cuda_fp16.h>
#include <cstdint>

// Problem constants (fixed by setup_inputs)
#define BB   4
#define NG   4096
#define DZ   128
#define NT   2048
#define KC   32           // g per chunk
#define NCH  (NG / KC)    // 128
#define NTHR 256

// Strides (bytes) in shared: 32 halves data + 8 halves pad = 80 B (bank-safe)
#define ROWB 80

// ---- shared layout (dynamic) ----
#define OFF_XG 0                       // 4096 float2 = 32768
#define OFF_W  32768                   // [2 buf][2 k][64 t][80B] = 20480
#define W_BUF  10240
#define W_K    5120
#define OFF_Z  (OFF_W + 2 * W_BUF)     // [3 buf][2 pass][128 z][80B] = 61440
#define Z_BUF  20480
#define Z_P    10240
#define SMEM_TOTAL (OFF_Z + 3 * Z_BUF)  // 114688

// ---- device scratch: z transposed K-major, fp16 hi/lo split (4 MB) ----
__device__ __half zt_hi[BB][DZ][NG];
__device__ __half zt_lo[BB][DZ][NG];

__device__ __forceinline__ uint32_t smem_u32(const void* p) {
    uint32_t a;
    asm("{ .reg .u64 t; cvta.to.shared.u64 t, %1; cvt.u32.u64 %0, t; }" : "=r"(a) : "l"(p));
    return a;
}

__device__ __forceinline__ void ldm4(uint32_t* r, uint32_t addr) {
    asm volatile("ldmatrix.sync.aligned.m8n8.x4.shared.b16 {%0,%1,%2,%3}, [%4];"
        : "=r"(r[0]), "=r"(r[1]), "=r"(r[2]), "=r"(r[3]) : "r"(addr));
}

__device__ __forceinline__ void mma16816(float* c, const uint32_t* a, const uint32_t* b) {
    asm volatile("mma.sync.aligned.m16n8k16.row.col.f32.f16.f16.f32 "
        "{%0,%1,%2,%3}, {%4,%5,%6,%7}, {%8,%9}, {%0,%1,%2,%3};"
        : "+f"(c[0]), "+f"(c[1]), "+f"(c[2]), "+f"(c[3])
        : "r"(a[0]), "r"(a[1]), "r"(a[2]), "r"(a[3]), "r"(b[0]), "r"(b[1]));
}

__device__ __forceinline__ void cp16(uint32_t dst, const void* src) {
    asm volatile("cp.async.cg.shared.global [%0], [%1], 16;" :: "r"(dst), "l"(src) : "memory");
}
#define CPA_COMMIT() asm volatile("cp.async.commit_group;" ::: "memory")
#define CPA_WAIT1()  asm volatile("cp.async.wait_group 1;" ::: "memory")

// fast exp2, degree-5 (rel err ~3e-7); y <= 0 expected
__device__ __forceinline__ float wexp(float y) {
    y = fmaxf(y, -125.0f);
    float zz = y + 12582912.0f;           // 1.5*2^23
    float n  = zz - 12582912.0f;
    float f  = y - n;
    float p = 1.3333558146e-3f;
    p = fmaf(p, f, 9.6181291076e-3f);
    p = fmaf(p, f, 5.5504108664e-2f);
    p = fmaf(p, f, 2.4022650696e-1f);
    p = fmaf(p, f, 6.9314718056e-1f);
    p = fmaf(p, f, 1.0f);
    float s = __int_as_float((__float_as_int(zz) << 23) + 0x3F800000);
    return p * s;
}

// ---- pre-kernel: transpose + fp16 hi/lo split ----
__global__ void __launch_bounds__(256)
prep_kernel(const float* __restrict__ zg) {
    __shared__ float tile[32][33];
    int b = blockIdx.z, g0 = blockIdx.x * 32, z0 = blockIdx.y * 32;
    const float* src = zg + ((size_t)b * NG + g0) * DZ + z0;
    int tx = threadIdx.x, ty = threadIdx.y;
    #pragma unroll
    for (int i = 0; i < 4; i++) {
        int gr = ty + i * 8;
        tile[gr][tx] = src[gr * DZ + tx];          // coalesced over z
    }
    __syncthreads();
    #pragma unroll
    for (int i = 0; i < 4; i++) {
        int zr = ty + i * 8;
        float v = tile[tx][zr];                    // g = tx, z = zr
        __half h = __float2half_rn(v);
        __half l = __float2half_rn(v - __half2float(h));
        zt_hi[b][z0 + zr][g0 + tx] = h;            // coalesced over g
        zt_lo[b][z0 + zr][g0 + tx] = l;
    }
}

__global__ void __launch_bounds__(NTHR, 1)
setconv_mma(const float* __restrict__ x_grid,   // (B, NG, 2)
            const float* __restrict__ xt,       // (B, NT, 2)
            const float* __restrict__ lsp,      // (2, 2)
            float* __restrict__ out)            // (B, NT, 256)
{
    extern __shared__ char smem[];
    const uint32_t sb = smem_u32(smem);
    const int tid  = threadIdx.x;
    const int wid  = tid >> 5;
    const int lane = tid & 31;

    const int cta = blockIdx.x;
    const int b   = cta >> 5;
    const int t0  = (cta & 31) * 64;

    const int mh = wid >> 2;        // m-half: rows mh*32 .. +31
    const int zq = (wid & 3) * 32;  // n-quarter: z zq .. +31

    // ---- load xg into smem (once) ----
    {
        const float4* src = (const float4*)(x_grid + (size_t)b * NG * 2);
        float4* dst = (float4*)(smem + OFF_XG);
        #pragma unroll
        for (int i = 0; i < 8; i++) dst[tid + i * NTHR] = src[tid + i * NTHR];
    }

    // ---- per-thread wgen identity ----
    const int wt = tid >> 2;            // t row 0..63
    const int gq = (tid & 3) * 8;       // g offset within chunk
    const float2 xtv = ((const float2*)xt)[(size_t)b * NT + t0 + wt];

    float cx0, cy0, cx1, cy1;
    {
        float l00 = 1e-5f + log1pf(expf(lsp[0]));
        float l01 = 1e-5f + log1pf(expf(lsp[1]));
        float l10 = 1e-5f + log1pf(expf(lsp[2]));
        float l11 = 1e-5f + log1pf(expf(lsp[3]));
        const float c = -0.5f * 1.44269504088896340736f;  // -0.5*log2(e)
        cx0 = c / (l00 * l00); cx1 = c / (l01 * l01);
        cy0 = c / (l10 * l10); cy1 = c / (l11 * l11);
    }

    const float2* xgs = (const float2*)(smem + OFF_XG);
    const uint32_t wstore = sb + OFF_W + (uint32_t)wt * ROWB + gq * 2;

    // wgen for chunk -> W[buf]
    auto wgen = [&](int chunk, int buf) {
        float w0[8], w1[8];
        #pragma unroll
        for (int j = 0; j < 8; j++) {
            float2 xv = xgs[chunk * KC + gq + j];
            float dx = xtv.x - xv.x, dy = xtv.y - xv.y;
            float dx2 = dx * dx, dy2 = dy * dy;
            w0[j] = wexp(fmaf(dx2, cx0, dy2 * cy0));
            w1[j] = wexp(fmaf(dx2, cx1, dy2 * cy1));
        }
        uint32_t h0[4], h1[4];
        #pragma unroll
        for (int q = 0; q < 4; q++) {
            __half2 a  = __floats2half2_rn(w0[2 * q], w0[2 * q + 1]);
            __half2 c2 = __floats2half2_rn(w1[2 * q], w1[2 * q + 1]);
            h0[q] = *reinterpret_cast<uint32_t*>(&a);
            h1[q] = *reinterpret_cast<uint32_t*>(&c2);
        }
        uint32_t wa = wstore + (uint32_t)buf * W_BUF;
        asm volatile("st.shared.v4.b32 [%0], {%1,%2,%3,%4};" :: "r"(wa),       "r"(h0[0]), "r"(h0[1]), "r"(h0[2]), "r"(h0[3]) : "memory");
        asm volatile("st.shared.v4.b32 [%0], {%1,%2,%3,%4};" :: "r"(wa + W_K), "r"(h1[0]), "r"(h1[1]), "r"(h1[2]), "r"(h1[3]) : "memory");
    };

    // cp.async Z chunk -> Z[buf] (always commit a group to keep counts aligned)
    auto loadz = [&](int chunk, int buf) {
        if (chunk < NCH) {
            #pragma unroll
            for (int ii = 0; ii < 4; ii++) {
                int i = tid + ii * NTHR;        // 0..1023
                int p = i >> 9;                 // 0 hi, 1 lo
                int w = i & 511;
                int z = w >> 2, j = w & 3;      // 4 x 16B per z-row
                const __half* src = (p ? zt_lo : zt_hi)[b][z] + chunk * KC + j * 8;
                cp16(sb + OFF_Z + (uint32_t)buf * Z_BUF + (uint32_t)p * Z_P
                     + (uint32_t)z * ROWB + j * 16, src);
            }
        }
        CPA_COMMIT();
    };

    // ---- ldmatrix lane address components ----
    const int r  = lane & 7;
    const int rb = (lane >> 3) & 1;
    const int cb = lane >> 4;
    // A: warp m-half included (mh*32 rows = 2560 B)  [round-11 bugfix]
    const uint32_t aRow = sb + OFF_W + (uint32_t)mh * 2560u
                        + (uint32_t)(r + rb * 8) * ROWB + cb * 16;
    // B: z-quarter rows; k-halves via rb
    const uint32_t bRow = sb + OFF_Z + (uint32_t)(zq + r + cb * 8) * ROWB + rb * 16;

    float acc[2][2][4][4];   // [k][mi][ni][reg]
    #pragma unroll
    for (int k = 0; k < 2; k++)
        #pragma unroll
        for (int mi = 0; mi < 2; mi++)
            #pragma unroll
            for (int ni = 0; ni < 4; ni++)
                #pragma unroll
                for (int j = 0; j < 4; j++) acc[k][mi][ni][j] = 0.0f;

    // ---- prologue ----
    loadz(0, 0);
    loadz(1, 1);
    __syncthreads();       // xg table ready
    wgen(0, 0);

    // ---- main loop ----
    for (int c = 0; c < NCH; c++) {
        const int bw = c & 1;        // W buffer
        const int bz = c % 3;        // Z buffer (triple: write target never read this iter)
        CPA_WAIT1();           // Z chunk c landed; chunk c+1 may be in flight
        __syncthreads();       // W[bw] written; prior readers of Z[(c+2)%3] done

        // A frags for both kernels
        uint32_t A[2][2][2][4];  // [k][mi][ks]
        #pragma unroll
        for (int k = 0; k < 2; k++)
            #pragma unroll
            for (int mi = 0; mi < 2; mi++)
                #pragma unroll
                for (int ks = 0; ks < 2; ks++)
                    ldm4(A[k][mi][ks],
                         aRow + (uint32_t)bw * W_BUF + (uint32_t)k * W_K + mi * 1280 + ks * 32);

        // hi + lo passes accumulate into same fp32 C
        #pragma unroll
        for (int p = 0; p < 2; p++) {
            uint32_t Bf[2][4][2];  // [ks][ni]
            #pragma unroll
            for (int ks = 0; ks < 2; ks++)
                #pragma unroll
                for (int np = 0; np < 2; np++)
                    ldm4(&Bf[ks][2 * np][0],
                         bRow + (uint32_t)bz * Z_BUF + (uint32_t)p * Z_P + np * 1280 + ks * 32);
            #pragma unroll
            for (int mi = 0; mi < 2; mi++)
                #pragma unroll
                for (int ni = 0; ni < 4; ni++)
                    #pragma unroll
                    for (int ks = 0; ks < 2; ks++) {
                        mma16816(acc[0][mi][ni], A[0][mi][ks], Bf[ks][ni]);
                        mma16816(acc[1][mi][ni], A[1][mi][ks], Bf[ks][ni]);
                    }
        }

        // prefetch chunk c+2 into Z[(c+2)%3] (not read this iter) + next weights
        loadz(c + 2, (c + 2) % 3);
        if (c + 1 < NCH) wgen(c + 1, bw ^ 1);
    }

    // ---- epilogue: direct stores, (k0,k1) packed per z ----
    float2* outp = (float2*)out + ((size_t)b * NT + t0) * 128;
    #pragma unroll
    for (int mi = 0; mi < 2; mi++)
        #pragma unroll
        for (int ni = 0; ni < 4; ni++)
            #pragma unroll
            for (int j = 0; j < 4; j++) {
                int row = mh * 32 + mi * 16 + (lane >> 2) + (j >> 1) * 8;
                int z   = zq + ni * 8 + 2 * (lane & 3) + (j & 1);
                outp[(size_t)row * 128 + z] =
                    make_float2(acc[0][mi][ni][j], acc[1][mi][ni][j]);
            }
}

extern "C" void kernel_launch(void* const* d_in, const int* in_sizes, int n_in,
                              void* d_out, int out_size) {
    (void)in_sizes; (void)n_in; (void)out_size;
    const float* x_grid = (const float*)d_in[0];
    const float* z_grid = (const float*)d_in[1];
    const float* xt     = (const float*)d_in[2];
    const float* lsp    = (const float*)d_in[3];
    float* out = (float*)d_out;

    prep_kernel<<<dim3(NG / 32, DZ / 32, BB), dim3(32, 8)>>>(z_grid);

    cudaFuncSetAttribute(setconv_mma, cudaFuncAttributeMaxDynamicSharedMemorySize, SMEM_TOTAL);
    setconv_mma<<<128, NTHR, SMEM_TOTAL>>>(x_grid, xt, lsp, out);
}

// round 16
// speedup vs baseline: 4.2856x; 1.3920x over previous
#include <cuda_runtime.h>
#include <cuda_fp16.h>
#include <cstdint>

// Problem constants (fixed by setup_inputs)
#define BB   4
#define NG   4096
#define DZ   128
#define NT   2048
#define KC   32           // g per chunk
#define NCH  (NG / KC)    // 128
#define NTHR 256

// Strides (bytes) in shared: 32 halves data + 8 halves pad = 80 B (bank-safe)
#define ROWB 80

// ---- shared layout (dynamic) ----
#define OFF_XG 0                       // 4096 float2 = 32768
#define OFF_W  32768                   // [2 buf][2 k][32 t][80B] = 10240
#define W_K    2560
#define W_BUF  5120
#define OFF_Z  (OFF_W + 2 * W_BUF)     // [3 buf][128 z][80B] = 30720
#define Z_BUF  10240
#define SMEM_TOTAL (OFF_Z + 3 * Z_BUF)  // 73728

// ---- device scratch: z transposed K-major fp16 (2 MB) ----
__device__ __half zt_hi[BB][DZ][NG];

__device__ __forceinline__ uint32_t smem_u32(const void* p) {
    uint32_t a;
    asm("{ .reg .u64 t; cvta.to.shared.u64 t, %1; cvt.u32.u64 %0, t; }" : "=r"(a) : "l"(p));
    return a;
}

__device__ __forceinline__ void ldm4(uint32_t* r, uint32_t addr) {
    asm volatile("ldmatrix.sync.aligned.m8n8.x4.shared.b16 {%0,%1,%2,%3}, [%4];"
        : "=r"(r[0]), "=r"(r[1]), "=r"(r[2]), "=r"(r[3]) : "r"(addr));
}

__device__ __forceinline__ void mma16816(float* c, const uint32_t* a, const uint32_t* b) {
    asm volatile("mma.sync.aligned.m16n8k16.row.col.f32.f16.f16.f32 "
        "{%0,%1,%2,%3}, {%4,%5,%6,%7}, {%8,%9}, {%0,%1,%2,%3};"
        : "+f"(c[0]), "+f"(c[1]), "+f"(c[2]), "+f"(c[3])
        : "r"(a[0]), "r"(a[1]), "r"(a[2]), "r"(a[3]), "r"(b[0]), "r"(b[1]));
}

__device__ __forceinline__ void cp16(uint32_t dst, const void* src) {
    asm volatile("cp.async.cg.shared.global [%0], [%1], 16;" :: "r"(dst), "l"(src) : "memory");
}
#define CPA_COMMIT() asm volatile("cp.async.commit_group;" ::: "memory")
#define CPA_WAIT1()  asm volatile("cp.async.wait_group 1;" ::: "memory")

// fast exp2, degree-5 (rel err ~3e-7); y <= 0 expected
__device__ __forceinline__ float wexp(float y) {
    y = fmaxf(y, -125.0f);
    float zz = y + 12582912.0f;           // 1.5*2^23
    float n  = zz - 12582912.0f;
    float f  = y - n;
    float p = 1.3333558146e-3f;
    p = fmaf(p, f, 9.6181291076e-3f);
    p = fmaf(p, f, 5.5504108664e-2f);
    p = fmaf(p, f, 2.4022650696e-1f);
    p = fmaf(p, f, 6.9314718056e-1f);
    p = fmaf(p, f, 1.0f);
    float s = __int_as_float((__float_as_int(zz) << 23) + 0x3F800000);
    return p * s;
}

// ---- pre-kernel: transpose to K-major fp16 ----
__global__ void __launch_bounds__(256)
prep_kernel(const float* __restrict__ zg) {
    __shared__ float tile[32][33];
    int b = blockIdx.z, g0 = blockIdx.x * 32, z0 = blockIdx.y * 32;
    const float* src = zg + ((size_t)b * NG + g0) * DZ + z0;
    int tx = threadIdx.x, ty = threadIdx.y;
    #pragma unroll
    for (int i = 0; i < 4; i++) {
        int gr = ty + i * 8;
        tile[gr][tx] = src[gr * DZ + tx];          // coalesced over z
    }
    __syncthreads();
    #pragma unroll
    for (int i = 0; i < 4; i++) {
        int zr = ty + i * 8;
        zt_hi[b][z0 + zr][g0 + tx] = __float2half_rn(tile[tx][zr]);  // coalesced over g
    }
}

__global__ void __launch_bounds__(NTHR, 2)
setconv_mma(const float* __restrict__ x_grid,   // (B, NG, 2)
            const float* __restrict__ xt,       // (B, NT, 2)
            const float* __restrict__ lsp,      // (2, 2)
            float* __restrict__ out)            // (B, NT, 256)
{
    extern __shared__ char smem[];
    const uint32_t sb = smem_u32(smem);
    const int tid  = threadIdx.x;
    const int wid  = tid >> 5;
    const int lane = tid & 31;

    const int cta = blockIdx.x;
    const int b   = cta >> 6;          // 64 CTAs per batch
    const int t0  = (cta & 63) * 32;   // 32-row t tile

    const int mh = wid >> 2;        // m-half: rows mh*16 .. +15
    const int zq = (wid & 3) * 32;  // n-quarter: z zq .. +31

    // ---- load xg into smem (once) ----
    {
        const float4* src = (const float4*)(x_grid + (size_t)b * NG * 2);
        float4* dst = (float4*)(smem + OFF_XG);
        #pragma unroll
        for (int i = 0; i < 8; i++) dst[tid + i * NTHR] = src[tid + i * NTHR];
    }

    // ---- per-thread wgen identity: t = tid>>3 (32 rows), 4 g per thread ----
    const int wt = tid >> 3;
    const int gq = (tid & 7) * 4;
    const float2 xtv = ((const float2*)xt)[(size_t)b * NT + t0 + wt];

    float cx0, cy0, cx1, cy1;
    {
        float l00 = 1e-5f + log1pf(expf(lsp[0]));
        float l01 = 1e-5f + log1pf(expf(lsp[1]));
        float l10 = 1e-5f + log1pf(expf(lsp[2]));
        float l11 = 1e-5f + log1pf(expf(lsp[3]));
        const float c = -0.5f * 1.44269504088896340736f;  // -0.5*log2(e)
        cx0 = c / (l00 * l00); cx1 = c / (l01 * l01);
        cy0 = c / (l10 * l10); cy1 = c / (l11 * l11);
    }

    const float2* xgs = (const float2*)(smem + OFF_XG);
    const uint32_t wstore = sb + OFF_W + (uint32_t)wt * ROWB + gq * 2;

    // wgen for chunk -> W[buf]  (4 g x 2 k = 8 exps per thread)
    auto wgen = [&](int chunk, int buf) {
        float w0[4], w1[4];
        #pragma unroll
        for (int j = 0; j < 4; j++) {
            float2 xv = xgs[chunk * KC + gq + j];
            float dx = xtv.x - xv.x, dy = xtv.y - xv.y;
            float dx2 = dx * dx, dy2 = dy * dy;
            w0[j] = wexp(fmaf(dx2, cx0, dy2 * cy0));
            w1[j] = wexp(fmaf(dx2, cx1, dy2 * cy1));
        }
        uint32_t h0[2], h1[2];
        #pragma unroll
        for (int q = 0; q < 2; q++) {
            __half2 a  = __floats2half2_rn(w0[2 * q], w0[2 * q + 1]);
            __half2 c2 = __floats2half2_rn(w1[2 * q], w1[2 * q + 1]);
            h0[q] = *reinterpret_cast<uint32_t*>(&a);
            h1[q] = *reinterpret_cast<uint32_t*>(&c2);
        }
        uint32_t wa = wstore + (uint32_t)buf * W_BUF;
        asm volatile("st.shared.v2.b32 [%0], {%1,%2};" :: "r"(wa),       "r"(h0[0]), "r"(h0[1]) : "memory");
        asm volatile("st.shared.v2.b32 [%0], {%1,%2};" :: "r"(wa + W_K), "r"(h1[0]), "r"(h1[1]) : "memory");
    };

    // cp.async Z chunk (fp16 hi only): 128 z x 64 B = 512 x 16B
    auto loadz = [&](int chunk, int buf) {
        if (chunk < NCH) {
            #pragma unroll
            for (int ii = 0; ii < 2; ii++) {
                int i = tid + ii * NTHR;        // 0..511
                int z = i >> 2, j = i & 3;
                const __half* src = zt_hi[b][z] + chunk * KC + j * 8;
                cp16(sb + OFF_Z + (uint32_t)buf * Z_BUF + (uint32_t)z * ROWB + j * 16, src);
            }
        }
        CPA_COMMIT();
    };

    // ---- ldmatrix lane address components ----
    const int r  = lane & 7;
    const int rb = (lane >> 3) & 1;
    const int cb = lane >> 4;
    // A: 16 rows (mh half of 32), 16 cols per ks
    const uint32_t aRow = sb + OFF_W + (uint32_t)mh * (16 * ROWB)
                        + (uint32_t)(r + rb * 8) * ROWB + cb * 16;
    // B: z rows of warp quarter
    const uint32_t bRow = sb + OFF_Z + (uint32_t)(zq + r + cb * 8) * ROWB + rb * 16;

    float acc[2][4][4];   // [k][ni][reg]
    #pragma unroll
    for (int k = 0; k < 2; k++)
        #pragma unroll
        for (int ni = 0; ni < 4; ni++)
            #pragma unroll
            for (int j = 0; j < 4; j++) acc[k][ni][j] = 0.0f;

    // ---- prologue ----
    loadz(0, 0);
    loadz(1, 1);
    __syncthreads();       // xg table ready
    wgen(0, 0);

    // ---- main loop ----
    for (int c = 0; c < NCH; c++) {
        const int bw = c & 1;        // W buffer
        const int bz = c % 3;        // Z buffer (triple: write target never read this iter)
        CPA_WAIT1();           // Z chunk c landed; chunk c+1 may be in flight
        __syncthreads();       // W[bw] written; prior readers of Z[(c+2)%3] done

        // A frags for both kernels
        uint32_t A[2][2][4];  // [k][ks]
        #pragma unroll
        for (int k = 0; k < 2; k++)
            #pragma unroll
            for (int ks = 0; ks < 2; ks++)
                ldm4(A[k][ks], aRow + (uint32_t)bw * W_BUF + (uint32_t)k * W_K + ks * 32);

        uint32_t Bf[2][4][2];  // [ks][ni]
        #pragma unroll
        for (int ks = 0; ks < 2; ks++)
            #pragma unroll
            for (int np = 0; np < 2; np++)
                ldm4(&Bf[ks][2 * np][0],
                     bRow + (uint32_t)bz * Z_BUF + np * (16 * ROWB) + ks * 32);

        #pragma unroll
        for (int ni = 0; ni < 4; ni++)
            #pragma unroll
            for (int ks = 0; ks < 2; ks++) {
                mma16816(acc[0][ni], A[0][ks], Bf[ks][ni]);
                mma16816(acc[1][ni], A[1][ks], Bf[ks][ni]);
            }

        // prefetch chunk c+2 into Z[(c+2)%3] (not read this iter) + next weights
        loadz(c + 2, (c + 2) % 3);
        if (c + 1 < NCH) wgen(c + 1, bw ^ 1);
    }

    // ---- epilogue: direct stores, (k0,k1) packed per z ----
    float2* outp = (float2*)out + ((size_t)b * NT + t0) * 128;
    #pragma unroll
    for (int ni = 0; ni < 4; ni++)
        #pragma unroll
        for (int j = 0; j < 4; j++) {
            int row = mh * 16 + (lane >> 2) + (j >> 1) * 8;
            int z   = zq + ni * 8 + 2 * (lane & 3) + (j & 1);
            outp[(size_t)row * 128 + z] = make_float2(acc[0][ni][j], acc[1][ni][j]);
        }
}

extern "C" void kernel_launch(void* const* d_in, const int* in_sizes, int n_in,
                              void* d_out, int out_size) {
    (void)in_sizes; (void)n_in; (void)out_size;
    const float* x_grid = (const float*)d_in[0];
    const float* z_grid = (const float*)d_in[1];
    const float* xt     = (const float*)d_in[2];
    const float* lsp    = (const float*)d_in[3];
    float* out = (float*)d_out;

    prep_kernel<<<dim3(NG / 32, DZ / 32, BB), dim3(32, 8)>>>(z_grid);

    cudaFuncSetAttribute(setconv_mma, cudaFuncAttributeMaxDynamicSharedMemorySize, SMEM_TOTAL);
    setconv_mma<<<256, NTHR, SMEM_TOTAL>>>(x_grid, xt, lsp, out);
}